// round 6
// baseline (speedup 1.0000x reference)
#include <cuda_runtime.h>
#include <cuda_bf16.h>
#include <cstdint>

#define N_TOK 8192
#define DM    1024
#define DF    4096
#define NE    8
#define MAX_TILES 71   // worst case: 64 + 7 partial tiles (128-row tiles)

// ---------------- scratch (static device, no allocations) ----------------
__device__ int   g_expert[N_TOK];
__device__ int   g_counts[NE];
__device__ int   g_offsets[NE + 1];
__device__ int   g_cursors[NE];
__device__ int   g_perm[N_TOK];
__device__ int   g_tile_prefix[NE + 1];

__device__ __nv_bfloat16 g_xh[(size_t)N_TOK * DM];
__device__ __nv_bfloat16 g_xl[(size_t)N_TOK * DM];
__device__ __nv_bfloat16 g_uwh[(size_t)NE * DF * DM];   // up W^T  [e][n=DF][k=DM]
__device__ __nv_bfloat16 g_uwl[(size_t)NE * DF * DM];
__device__ __nv_bfloat16 g_dwh[(size_t)NE * DM * DF];   // down W^T [e][n=DM][k=DF]
__device__ __nv_bfloat16 g_dwl[(size_t)NE * DM * DF];
__device__ __nv_bfloat16 g_hh[(size_t)N_TOK * DF];
__device__ __nv_bfloat16 g_hl[(size_t)N_TOK * DF];

// ---------------- PTX helpers (baseline ISA only) ----------------
__device__ __forceinline__ uint32_t smem_u32(const void* p) {
    uint32_t a;
    asm("{ .reg .u64 t; cvta.to.shared.u64 t, %1; cvt.u32.u64 %0, t; }" : "=r"(a) : "l"(p));
    return a;
}
__device__ __forceinline__ void cp_async16(uint32_t dst, const void* src) {
    asm volatile("cp.async.cg.shared.global [%0], [%1], 16;"
                 :: "r"(dst), "l"(__cvta_generic_to_global(src)));
}
__device__ __forceinline__ void cp_commit() {
    asm volatile("cp.async.commit_group;");
}
template <int N>
__device__ __forceinline__ void cp_wait() {
    asm volatile("cp.async.wait_group %0;" :: "n"(N));
}
#define LDSM4(r0, r1, r2, r3, addr)                                            \
    asm volatile("ldmatrix.sync.aligned.m8n8.x4.shared.b16 {%0,%1,%2,%3}, [%4];" \
                 : "=r"(r0), "=r"(r1), "=r"(r2), "=r"(r3) : "r"(addr))
#define MMA16816(c, a0, a1, a2, a3, b0, b1)                                    \
    asm volatile("mma.sync.aligned.m16n8k16.row.col.f32.bf16.bf16.f32 "        \
                 "{%0,%1,%2,%3},{%4,%5,%6,%7},{%8,%9},{%0,%1,%2,%3};"          \
                 : "+f"((c)[0]), "+f"((c)[1]), "+f"((c)[2]), "+f"((c)[3])      \
                 : "r"(a0), "r"(a1), "r"(a2), "r"(a3), "r"(b0), "r"(b1))

__device__ __forceinline__ void split_f32(float v, __nv_bfloat16& h, __nv_bfloat16& l) {
    h = __float2bfloat16(v);
    l = __float2bfloat16(v - __bfloat162float(h));
}

// ---------------- routing kernels ----------------
__global__ void init_kernel() {
    int t = threadIdx.x;
    if (t < NE) { g_counts[t] = 0; g_cursors[t] = 0; }
}

__global__ void gate_kernel(const float* __restrict__ x,
                            const float* __restrict__ gW,
                            const float* __restrict__ gb,
                            float* gate_out) {
    int tok  = (blockIdx.x * blockDim.x + threadIdx.x) >> 5;
    int lane = threadIdx.x & 31;
    if (tok >= N_TOK) return;
    const float* xr = x + (size_t)tok * DM;
    float acc[NE];
#pragma unroll
    for (int e = 0; e < NE; e++) acc[e] = 0.f;
    for (int k = lane; k < DM; k += 32) {
        float xv = xr[k];
        const float* w = gW + k * NE;
#pragma unroll
        for (int e = 0; e < NE; e++) acc[e] += xv * w[e];
    }
#pragma unroll
    for (int e = 0; e < NE; e++) {
#pragma unroll
        for (int o = 16; o; o >>= 1) acc[e] += __shfl_xor_sync(0xffffffffu, acc[e], o);
        acc[e] += gb[e];
    }
    int best = 0;
#pragma unroll
    for (int e = 1; e < NE; e++) if (acc[e] > acc[best]) best = e;
    if (lane == 0) {
        g_expert[tok] = best;
        atomicAdd(&g_counts[best], 1);
    }
    if (gate_out && lane < NE)
        gate_out[(size_t)tok * NE + lane] = (lane == best) ? 1.0f : 0.0f;
}

__global__ void scan_kernel() {
    int s = 0, tp = 0;
    for (int e = 0; e < NE; e++) {
        g_offsets[e] = s;
        g_tile_prefix[e] = tp;
        tp += (g_counts[e] + 127) >> 7;
        s += g_counts[e];
    }
    g_offsets[NE] = s;
    g_tile_prefix[NE] = tp;
}

__global__ void scatter_kernel() {
    int t = blockIdx.x * blockDim.x + threadIdx.x;
    if (t >= N_TOK) return;
    int e = g_expert[t];
    int pos = g_offsets[e] + atomicAdd(&g_cursors[e], 1);
    g_perm[pos] = t;
}

// ---------------- conversions ----------------
__global__ void conv_x_kernel(const float* __restrict__ x) {
    int p = blockIdx.x;
    int t = threadIdx.x;
    int tok = g_perm[p];
    float4 v = ((const float4*)(x + (size_t)tok * DM))[t];
    __nv_bfloat16 h0, h1, h2, h3, l0, l1, l2, l3;
    split_f32(v.x, h0, l0); split_f32(v.y, h1, l1);
    split_f32(v.z, h2, l2); split_f32(v.w, h3, l3);
    __nv_bfloat162* dh = (__nv_bfloat162*)(g_xh + (size_t)p * DM);
    __nv_bfloat162* dl = (__nv_bfloat162*)(g_xl + (size_t)p * DM);
    dh[2 * t]     = __nv_bfloat162(h0, h1);
    dh[2 * t + 1] = __nv_bfloat162(h2, h3);
    dl[2 * t]     = __nv_bfloat162(l0, l1);
    dl[2 * t + 1] = __nv_bfloat162(l2, l3);
}

// W: [e][K][N] fp32  ->  T: [e][N][K] bf16 hi/lo
template <bool UP>
__global__ void conv_w_kernel(const float* __restrict__ W, int K, int N) {
    __shared__ float tile[32][33];
    __nv_bfloat16* Th = UP ? g_uwh : g_dwh;
    __nv_bfloat16* Tl = UP ? g_uwl : g_dwl;
    int e  = blockIdx.z;
    int n0 = blockIdx.x * 32;
    int k0 = blockIdx.y * 32;
    int tx = threadIdx.x, ty = threadIdx.y;
    const float* Wp = W + (size_t)e * K * N;
#pragma unroll
    for (int i = 0; i < 4; i++)
        tile[ty + i * 8][tx] = Wp[(size_t)(k0 + ty + i * 8) * N + n0 + tx];
    __syncthreads();
    size_t base = (size_t)e * N * K;
#pragma unroll
    for (int i = 0; i < 4; i++) {
        float v = tile[tx][ty + i * 8];
        __nv_bfloat16 h, l;
        split_f32(v, h, l);
        size_t idx = base + (size_t)(n0 + ty + i * 8) * K + k0 + tx;
        Th[idx] = h;
        Tl[idx] = l;
    }
}

// ---------------- HMMA grouped GEMM ----------------
// CTA tile 128(M) x 256(N) x 32(K-chunk). 512 threads, 16 warps (4m x 4n), warp tile 32x64.
// SMEM stage: Ah(128), Al(128), Bh(256), Bl(256) rows x 80B (64B data + 16B pad) = 61440 B.
// 3-stage pipeline with cp.async.wait_group 1 -> one full stage always in flight.
#define ROW_B    80
#define OFF_AH   0
#define OFF_AL   (128 * ROW_B)            // 10240
#define OFF_BH   (256 * ROW_B)            // 20480
#define OFF_BL   (OFF_BH + 256 * ROW_B)   // 40960
#define STAGE_B  (OFF_BL + 256 * ROW_B)   // 61440
#define NSTAGE   3
#define SMEM_BYTES (NSTAGE * STAGE_B)     // 184320

template <bool IS_UP>
__global__ void __launch_bounds__(512, 1)
gemm_kernel(const float* __restrict__ bias, float* __restrict__ out) {
    constexpr int K   = IS_UP ? DM : DF;
    constexpr int NT  = IS_UP ? DF : DM;
    constexpr int NCH = K / 32;

    int ty = blockIdx.y;
    if (ty >= g_tile_prefix[NE]) return;
    int e = 0;
    while (ty >= g_tile_prefix[e + 1]) e++;
    int off = g_offsets[e];
    int cnt = g_offsets[e + 1] - off;
    int m0  = (ty - g_tile_prefix[e]) * 128;
    int n0  = blockIdx.x * 256;
    int valid = cnt - m0; if (valid > 128) valid = 128;

    extern __shared__ char smem[];
    uint32_t sb = smem_u32(smem);

    int tid = threadIdx.x, lane = tid & 31, wid = tid >> 5;
    int wm = (wid & 3) * 32;        // 0,32,64,96
    int wn = (wid >> 2) * 64;       // 0,64,128,192
    int g = lane >> 2, t4 = lane & 3;

    const __nv_bfloat16* Ah = (IS_UP ? g_xh  : g_hh)  + (size_t)(off + m0) * K;
    const __nv_bfloat16* Al = (IS_UP ? g_xl  : g_hl)  + (size_t)(off + m0) * K;
    const __nv_bfloat16* Bh = (IS_UP ? g_uwh : g_dwh) + ((size_t)e * NT + n0) * K;
    const __nv_bfloat16* Bl = (IS_UP ? g_uwl : g_dwl) + ((size_t)e * NT + n0) * K;

    float acc[2][8][4];
#pragma unroll
    for (int i = 0; i < 2; i++)
#pragma unroll
        for (int j = 0; j < 8; j++)
#pragma unroll
            for (int r = 0; r < 4; r++) acc[i][j][r] = 0.f;

    // loader: 3072 16B-chunks per stage, 6 per thread
    auto load_chunk = [&](int c, int st) {
        int rbase = tid >> 2;          // 0..127
        int seg   = tid & 3;           // 0..3
        uint32_t dstb = sb + st * STAGE_B + seg * 16;
        int col = c * 32 + seg * 8;
        int ra = (rbase < valid) ? rbase : 0;     // dup-safe A clamp
        cp_async16(dstb + OFF_AH + (uint32_t)rbase * ROW_B, Ah + (size_t)ra * K + col);
        cp_async16(dstb + OFF_AL + (uint32_t)rbase * ROW_B, Al + (size_t)ra * K + col);
        cp_async16(dstb + OFF_BH + (uint32_t)rbase * ROW_B, Bh + (size_t)rbase * K + col);
        cp_async16(dstb + OFF_BH + (uint32_t)(rbase + 128) * ROW_B,
                   Bh + (size_t)(rbase + 128) * K + col);
        cp_async16(dstb + OFF_BL + (uint32_t)rbase * ROW_B, Bl + (size_t)rbase * K + col);
        cp_async16(dstb + OFF_BL + (uint32_t)(rbase + 128) * ROW_B,
                   Bl + (size_t)(rbase + 128) * K + col);
    };

    load_chunk(0, 0); cp_commit();
    load_chunk(1, 1); cp_commit();

    for (int c = 0; c < NCH; c++) {
        cp_wait<1>();
        __syncthreads();
        if (c + 2 < NCH) load_chunk(c + 2, (c + 2) % NSTAGE);
        cp_commit();   // empty groups at tail keep FIFO semantics aligned

        uint32_t stb = sb + (c % NSTAGE) * STAGE_B;
#pragma unroll
        for (int kk = 0; kk < 2; kk++) {
            uint32_t kb = kk * 32;
            // A hi
            uint32_t ah[2][4];
#pragma unroll
            for (int mi = 0; mi < 2; mi++) {
                uint32_t rb = stb + OFF_AH
                            + (uint32_t)(wm + mi * 16 + (lane & 15)) * ROW_B
                            + kb + ((lane >> 4) & 1) * 16;
                LDSM4(ah[mi][0], ah[mi][1], ah[mi][2], ah[mi][3], rb);
            }
            // B hi
            uint32_t bh[8][2];
#pragma unroll
            for (int p = 0; p < 4; p++) {
                uint32_t rb = stb + OFF_BH
                            + (uint32_t)(wn + p * 16 + ((lane >> 4) & 1) * 8 + (lane & 7)) * ROW_B
                            + kb + ((lane >> 3) & 1) * 16;
                LDSM4(bh[2 * p][0], bh[2 * p][1], bh[2 * p + 1][0], bh[2 * p + 1][1], rb);
            }
            // P1 = Ah * Bh
#pragma unroll
            for (int mi = 0; mi < 2; mi++)
#pragma unroll
                for (int ni = 0; ni < 8; ni++)
                    MMA16816(acc[mi][ni], ah[mi][0], ah[mi][1], ah[mi][2], ah[mi][3],
                             bh[ni][0], bh[ni][1]);
            // A lo, P2 = Al * Bh
            {
                uint32_t al[2][4];
#pragma unroll
                for (int mi = 0; mi < 2; mi++) {
                    uint32_t rb = stb + OFF_AL
                                + (uint32_t)(wm + mi * 16 + (lane & 15)) * ROW_B
                                + kb + ((lane >> 4) & 1) * 16;
                    LDSM4(al[mi][0], al[mi][1], al[mi][2], al[mi][3], rb);
                }
#pragma unroll
                for (int mi = 0; mi < 2; mi++)
#pragma unroll
                    for (int ni = 0; ni < 8; ni++)
                        MMA16816(acc[mi][ni], al[mi][0], al[mi][1], al[mi][2], al[mi][3],
                                 bh[ni][0], bh[ni][1]);
            }
            // B lo, P3 = Ah * Bl (reuses bh storage)
#pragma unroll
            for (int p = 0; p < 4; p++) {
                uint32_t rb = stb + OFF_BL
                            + (uint32_t)(wn + p * 16 + ((lane >> 4) & 1) * 8 + (lane & 7)) * ROW_B
                            + kb + ((lane >> 3) & 1) * 16;
                LDSM4(bh[2 * p][0], bh[2 * p][1], bh[2 * p + 1][0], bh[2 * p + 1][1], rb);
            }
#pragma unroll
            for (int mi = 0; mi < 2; mi++)
#pragma unroll
                for (int ni = 0; ni < 8; ni++)
                    MMA16816(acc[mi][ni], ah[mi][0], ah[mi][1], ah[mi][2], ah[mi][3],
                             bh[ni][0], bh[ni][1]);
        }
    }

    // ---------------- epilogue (direct global stores) ----------------
    const float* bptr = bias + (size_t)e * NT + n0;
#pragma unroll
    for (int mi = 0; mi < 2; mi++) {
#pragma unroll
        for (int rr = 0; rr < 2; rr++) {
            int m = wm + mi * 16 + g + rr * 8;
            if (m >= valid) continue;
            if (IS_UP) {
                size_t pos = (size_t)(off + m0 + m);
                __nv_bfloat16* hrow = g_hh + pos * DF + n0;
                __nv_bfloat16* lrow = g_hl + pos * DF + n0;
#pragma unroll
                for (int ni = 0; ni < 8; ni++) {
                    int bn = wn + ni * 8 + 2 * t4;
                    float v0 = acc[mi][ni][rr * 2 + 0] + bptr[bn];
                    float v1 = acc[mi][ni][rr * 2 + 1] + bptr[bn + 1];
                    v0 = v0 > 0.f ? v0 : 0.f;
                    v1 = v1 > 0.f ? v1 : 0.f;
                    __nv_bfloat16 h0, l0, h1, l1;
                    split_f32(v0, h0, l0);
                    split_f32(v1, h1, l1);
                    *(__nv_bfloat162*)(hrow + bn) = __nv_bfloat162(h0, h1);
                    *(__nv_bfloat162*)(lrow + bn) = __nv_bfloat162(l0, l1);
                }
            } else {
                int tok = g_perm[off + m0 + m];
                float* orow = out + (size_t)tok * DM + n0;
#pragma unroll
                for (int ni = 0; ni < 8; ni++) {
                    int bn = wn + ni * 8 + 2 * t4;
                    float2 v;
                    v.x = acc[mi][ni][rr * 2 + 0] + bptr[bn];
                    v.y = acc[mi][ni][rr * 2 + 1] + bptr[bn + 1];
                    *(float2*)(orow + bn) = v;
                }
            }
        }
    }
}

// ---------------- launch ----------------
extern "C" void kernel_launch(void* const* d_in, const int* in_sizes, int n_in,
                              void* d_out, int out_size) {
    const float* x   = (const float*)d_in[0];
    const float* gW  = (const float*)d_in[1];
    const float* gb  = (const float*)d_in[2];
    const float* upW = (const float*)d_in[3];
    const float* upb = (const float*)d_in[4];
    const float* dW  = (const float*)d_in[5];
    const float* db  = (const float*)d_in[6];
    float* out = (float*)d_out;

    float* gate_out = nullptr;
    if (out_size >= N_TOK * DM + N_TOK * NE)
        gate_out = out + (size_t)out_size - (size_t)N_TOK * NE;

    cudaFuncSetAttribute(gemm_kernel<true>,  cudaFuncAttributeMaxDynamicSharedMemorySize, SMEM_BYTES);
    cudaFuncSetAttribute(gemm_kernel<false>, cudaFuncAttributeMaxDynamicSharedMemorySize, SMEM_BYTES);

    init_kernel<<<1, 32>>>();
    gate_kernel<<<N_TOK / 8, 256>>>(x, gW, gb, gate_out);
    scan_kernel<<<1, 1>>>();
    scatter_kernel<<<N_TOK / 256, 256>>>();
    conv_x_kernel<<<N_TOK, 256>>>(x);

    dim3 b32(32, 8);
    conv_w_kernel<true><<<dim3(DF / 32, DM / 32, NE), b32>>>(upW, DM, DF);
    conv_w_kernel<false><<<dim3(DM / 32, DF / 32, NE), b32>>>(dW, DF, DM);

    gemm_kernel<true><<<dim3(DF / 256, MAX_TILES), 512, SMEM_BYTES>>>(upb, nullptr);
    gemm_kernel<false><<<dim3(DM / 256, MAX_TILES), 512, SMEM_BYTES>>>(db, out);
}

// round 7
// speedup vs baseline: 1.5147x; 1.5147x over previous
#include <cuda_runtime.h>
#include <cuda_fp16.h>
#include <cstdint>

#define N_TOK 8192
#define DM    1024
#define DF    4096
#define NE    8
#define MAX_TILES 71   // worst case: 64 + 7 partial tiles (128-row tiles)

// ---------------- scratch (static device, no allocations) ----------------
__device__ int   g_expert[N_TOK];
__device__ int   g_counts[NE];
__device__ int   g_offsets[NE + 1];
__device__ int   g_cursors[NE];
__device__ int   g_perm[N_TOK];
__device__ int   g_tile_prefix[NE + 1];

__device__ __half g_xh[(size_t)N_TOK * DM];
__device__ __half g_xl[(size_t)N_TOK * DM];
__device__ __half g_uw[(size_t)NE * DF * DM];   // up W^T  [e][n=DF][k=DM], single fp16
__device__ __half g_dw[(size_t)NE * DM * DF];   // down W^T [e][n=DM][k=DF], single fp16
__device__ __half g_hh[(size_t)N_TOK * DF];
__device__ __half g_hl[(size_t)N_TOK * DF];

// ---------------- PTX helpers (baseline ISA only) ----------------
__device__ __forceinline__ uint32_t smem_u32(const void* p) {
    uint32_t a;
    asm("{ .reg .u64 t; cvta.to.shared.u64 t, %1; cvt.u32.u64 %0, t; }" : "=r"(a) : "l"(p));
    return a;
}
__device__ __forceinline__ void cp_async16(uint32_t dst, const void* src) {
    asm volatile("cp.async.cg.shared.global [%0], [%1], 16;"
                 :: "r"(dst), "l"(__cvta_generic_to_global(src)));
}
__device__ __forceinline__ void cp_commit() {
    asm volatile("cp.async.commit_group;");
}
template <int N>
__device__ __forceinline__ void cp_wait() {
    asm volatile("cp.async.wait_group %0;" :: "n"(N));
}
#define LDSM4(r0, r1, r2, r3, addr)                                            \
    asm volatile("ldmatrix.sync.aligned.m8n8.x4.shared.b16 {%0,%1,%2,%3}, [%4];" \
                 : "=r"(r0), "=r"(r1), "=r"(r2), "=r"(r3) : "r"(addr))
#define MMA16816(c, a0, a1, a2, a3, b0, b1)                                    \
    asm volatile("mma.sync.aligned.m16n8k16.row.col.f32.f16.f16.f32 "          \
                 "{%0,%1,%2,%3},{%4,%5,%6,%7},{%8,%9},{%0,%1,%2,%3};"          \
                 : "+f"((c)[0]), "+f"((c)[1]), "+f"((c)[2]), "+f"((c)[3])      \
                 : "r"(a0), "r"(a1), "r"(a2), "r"(a3), "r"(b0), "r"(b1))

__device__ __forceinline__ void split_f32h(float v, __half& h, __half& l) {
    h = __float2half(v);
    l = __float2half(v - __half2float(h));
}

// ---------------- routing kernels ----------------
__global__ void init_kernel() {
    int t = threadIdx.x;
    if (t < NE) { g_counts[t] = 0; g_cursors[t] = 0; }
}

__global__ void gate_kernel(const float* __restrict__ x,
                            const float* __restrict__ gW,
                            const float* __restrict__ gb,
                            float* gate_out) {
    int tok  = (blockIdx.x * blockDim.x + threadIdx.x) >> 5;
    int lane = threadIdx.x & 31;
    if (tok >= N_TOK) return;
    const float* xr = x + (size_t)tok * DM;
    float acc[NE];
#pragma unroll
    for (int e = 0; e < NE; e++) acc[e] = 0.f;
    for (int k = lane; k < DM; k += 32) {
        float xv = xr[k];
        const float* w = gW + k * NE;
#pragma unroll
        for (int e = 0; e < NE; e++) acc[e] += xv * w[e];
    }
#pragma unroll
    for (int e = 0; e < NE; e++) {
#pragma unroll
        for (int o = 16; o; o >>= 1) acc[e] += __shfl_xor_sync(0xffffffffu, acc[e], o);
        acc[e] += gb[e];
    }
    int best = 0;
#pragma unroll
    for (int e = 1; e < NE; e++) if (acc[e] > acc[best]) best = e;
    if (lane == 0) {
        g_expert[tok] = best;
        atomicAdd(&g_counts[best], 1);
    }
    if (gate_out && lane < NE)
        gate_out[(size_t)tok * NE + lane] = (lane == best) ? 1.0f : 0.0f;
}

__global__ void scan_kernel() {
    int s = 0, tp = 0;
    for (int e = 0; e < NE; e++) {
        g_offsets[e] = s;
        g_tile_prefix[e] = tp;
        tp += (g_counts[e] + 127) >> 7;
        s += g_counts[e];
    }
    g_offsets[NE] = s;
    g_tile_prefix[NE] = tp;
}

__global__ void scatter_kernel() {
    int t = blockIdx.x * blockDim.x + threadIdx.x;
    if (t >= N_TOK) return;
    int e = g_expert[t];
    int pos = g_offsets[e] + atomicAdd(&g_cursors[e], 1);
    g_perm[pos] = t;
}

// ---------------- conversions ----------------
__global__ void conv_x_kernel(const float* __restrict__ x) {
    int p = blockIdx.x;
    int t = threadIdx.x;
    int tok = g_perm[p];
    float4 v = ((const float4*)(x + (size_t)tok * DM))[t];
    __half h0, h1, h2, h3, l0, l1, l2, l3;
    split_f32h(v.x, h0, l0); split_f32h(v.y, h1, l1);
    split_f32h(v.z, h2, l2); split_f32h(v.w, h3, l3);
    __half2* dh = (__half2*)(g_xh + (size_t)p * DM);
    __half2* dl = (__half2*)(g_xl + (size_t)p * DM);
    dh[2 * t]     = __half2(h0, h1);
    dh[2 * t + 1] = __half2(h2, h3);
    dl[2 * t]     = __half2(l0, l1);
    dl[2 * t + 1] = __half2(l2, l3);
}

// W: [e][K][N] fp32  ->  T: [e][N][K] fp16 (single tensor)
template <bool UP>
__global__ void conv_w_kernel(const float* __restrict__ W, int K, int N) {
    __shared__ float tile[32][33];
    __half* T = UP ? g_uw : g_dw;
    int e  = blockIdx.z;
    int n0 = blockIdx.x * 32;
    int k0 = blockIdx.y * 32;
    int tx = threadIdx.x, ty = threadIdx.y;
    const float* Wp = W + (size_t)e * K * N;
#pragma unroll
    for (int i = 0; i < 4; i++)
        tile[ty + i * 8][tx] = Wp[(size_t)(k0 + ty + i * 8) * N + n0 + tx];
    __syncthreads();
    size_t base = (size_t)e * N * K;
#pragma unroll
    for (int i = 0; i < 4; i++) {
        float v = tile[tx][ty + i * 8];
        T[base + (size_t)(n0 + ty + i * 8) * K + k0 + tx] = __float2half(v);
    }
}

// ---------------- HMMA grouped GEMM (fp16, 2-product split of A) ----------------
// CTA tile 128(M) x 256(N) x 64(K-chunk). 512 threads, 16 warps (4m x 4n), warp tile 32x64.
// SMEM stage: Ah(128) + Al(128) + B(256) rows x 144B (128B data + 16B pad) = 73728 B.
// 3-stage pipeline, cp.async.wait_group 1 -> one full stage always in flight.
#define ROW_B    144
#define OFF_AH   0
#define OFF_AL   (128 * ROW_B)            // 18432
#define OFF_B    (256 * ROW_B)            // 36864
#define STAGE_B  (OFF_B + 256 * ROW_B)    // 73728
#define NSTAGE   3
#define SMEM_BYTES (NSTAGE * STAGE_B)     // 221184

template <bool IS_UP>
__global__ void __launch_bounds__(512, 1)
gemm_kernel(const float* __restrict__ bias, float* __restrict__ out) {
    constexpr int K   = IS_UP ? DM : DF;
    constexpr int NT  = IS_UP ? DF : DM;
    constexpr int NCH = K / 64;

    int ty = blockIdx.y;
    if (ty >= g_tile_prefix[NE]) return;
    int e = 0;
    while (ty >= g_tile_prefix[e + 1]) e++;
    int off = g_offsets[e];
    int cnt = g_offsets[e + 1] - off;
    int m0  = (ty - g_tile_prefix[e]) * 128;
    int n0  = blockIdx.x * 256;
    int valid = cnt - m0; if (valid > 128) valid = 128;

    extern __shared__ char smem[];
    uint32_t sb = smem_u32(smem);

    int tid = threadIdx.x, lane = tid & 31, wid = tid >> 5;
    int wm = (wid & 3) * 32;        // 0,32,64,96
    int wn = (wid >> 2) * 64;       // 0,64,128,192
    int g = lane >> 2, t4 = lane & 3;

    const __half* Ah = (IS_UP ? g_xh : g_hh) + (size_t)(off + m0) * K;
    const __half* Al = (IS_UP ? g_xl : g_hl) + (size_t)(off + m0) * K;
    const __half* Bp = (IS_UP ? g_uw : g_dw) + ((size_t)e * NT + n0) * K;

    float acc[2][8][4];
#pragma unroll
    for (int i = 0; i < 2; i++)
#pragma unroll
        for (int j = 0; j < 8; j++)
#pragma unroll
            for (int r = 0; r < 4; r++) acc[i][j][r] = 0.f;

    // loader: stage = 512 rows x 128B = 4096 x 16B chunks, 8 per thread.
    // i<2: Ah rows, i in {2,3}: Al rows, i>=4: B rows (0..255).
    auto load_chunk = [&](int c, int st) {
        int r0  = tid >> 3;            // 0..63
        int seg = tid & 7;             // 0..7
        uint32_t dstb = sb + st * STAGE_B + seg * 16;
        int col = c * 64 + seg * 8;
#pragma unroll
        for (int i = 0; i < 8; i++) {
            int lrow = r0 + (i & ((i < 4) ? 1 : 3)) * 64;   // Ah/Al: 0..127, B: 0..255
            if (i < 2) {
                int ra = (lrow < valid) ? lrow : 0;
                cp_async16(dstb + OFF_AH + (uint32_t)lrow * ROW_B, Ah + (size_t)ra * K + col);
            } else if (i < 4) {
                int ra = (lrow < valid) ? lrow : 0;
                cp_async16(dstb + OFF_AL + (uint32_t)lrow * ROW_B, Al + (size_t)ra * K + col);
            } else {
                cp_async16(dstb + OFF_B + (uint32_t)lrow * ROW_B, Bp + (size_t)lrow * K + col);
            }
        }
    };

    load_chunk(0, 0); cp_commit();
    load_chunk(1, 1); cp_commit();

    for (int c = 0; c < NCH; c++) {
        cp_wait<1>();
        __syncthreads();
        if (c + 2 < NCH) load_chunk(c + 2, (c + 2) % NSTAGE);
        cp_commit();   // empty groups at tail keep FIFO count aligned

        uint32_t stb = sb + (c % NSTAGE) * STAGE_B;
#pragma unroll
        for (int kk = 0; kk < 4; kk++) {
            uint32_t kb = kk * 32;
            // A hi
            uint32_t ah[2][4];
#pragma unroll
            for (int mi = 0; mi < 2; mi++) {
                uint32_t rb = stb + OFF_AH
                            + (uint32_t)(wm + mi * 16 + (lane & 15)) * ROW_B
                            + kb + ((lane >> 4) & 1) * 16;
                LDSM4(ah[mi][0], ah[mi][1], ah[mi][2], ah[mi][3], rb);
            }
            // B
            uint32_t bf[8][2];
#pragma unroll
            for (int p = 0; p < 4; p++) {
                uint32_t rb = stb + OFF_B
                            + (uint32_t)(wn + p * 16 + ((lane >> 4) & 1) * 8 + (lane & 7)) * ROW_B
                            + kb + ((lane >> 3) & 1) * 16;
                LDSM4(bf[2 * p][0], bf[2 * p][1], bf[2 * p + 1][0], bf[2 * p + 1][1], rb);
            }
            // P1 = Ah * B
#pragma unroll
            for (int mi = 0; mi < 2; mi++)
#pragma unroll
                for (int ni = 0; ni < 8; ni++)
                    MMA16816(acc[mi][ni], ah[mi][0], ah[mi][1], ah[mi][2], ah[mi][3],
                             bf[ni][0], bf[ni][1]);
            // A lo, P2 = Al * B
            {
                uint32_t al[2][4];
#pragma unroll
                for (int mi = 0; mi < 2; mi++) {
                    uint32_t rb = stb + OFF_AL
                                + (uint32_t)(wm + mi * 16 + (lane & 15)) * ROW_B
                                + kb + ((lane >> 4) & 1) * 16;
                    LDSM4(al[mi][0], al[mi][1], al[mi][2], al[mi][3], rb);
                }
#pragma unroll
                for (int mi = 0; mi < 2; mi++)
#pragma unroll
                    for (int ni = 0; ni < 8; ni++)
                        MMA16816(acc[mi][ni], al[mi][0], al[mi][1], al[mi][2], al[mi][3],
                                 bf[ni][0], bf[ni][1]);
            }
        }
    }

    // ---------------- epilogue (direct global stores) ----------------
    const float* bptr = bias + (size_t)e * NT + n0;
#pragma unroll
    for (int mi = 0; mi < 2; mi++) {
#pragma unroll
        for (int rr = 0; rr < 2; rr++) {
            int m = wm + mi * 16 + g + rr * 8;
            if (m >= valid) continue;
            if (IS_UP) {
                size_t pos = (size_t)(off + m0 + m);
                __half* hrow = g_hh + pos * DF + n0;
                __half* lrow = g_hl + pos * DF + n0;
#pragma unroll
                for (int ni = 0; ni < 8; ni++) {
                    int bn = wn + ni * 8 + 2 * t4;
                    float v0 = acc[mi][ni][rr * 2 + 0] + bptr[bn];
                    float v1 = acc[mi][ni][rr * 2 + 1] + bptr[bn + 1];
                    v0 = v0 > 0.f ? v0 : 0.f;
                    v1 = v1 > 0.f ? v1 : 0.f;
                    __half h0, l0, h1, l1;
                    split_f32h(v0, h0, l0);
                    split_f32h(v1, h1, l1);
                    *(__half2*)(hrow + bn) = __half2(h0, h1);
                    *(__half2*)(lrow + bn) = __half2(l0, l1);
                }
            } else {
                int tok = g_perm[off + m0 + m];
                float* orow = out + (size_t)tok * DM + n0;
#pragma unroll
                for (int ni = 0; ni < 8; ni++) {
                    int bn = wn + ni * 8 + 2 * t4;
                    float2 v;
                    v.x = acc[mi][ni][rr * 2 + 0] + bptr[bn];
                    v.y = acc[mi][ni][rr * 2 + 1] + bptr[bn + 1];
                    *(float2*)(orow + bn) = v;
                }
            }
        }
    }
}

// ---------------- launch ----------------
extern "C" void kernel_launch(void* const* d_in, const int* in_sizes, int n_in,
                              void* d_out, int out_size) {
    const float* x   = (const float*)d_in[0];
    const float* gW  = (const float*)d_in[1];
    const float* gb  = (const float*)d_in[2];
    const float* upW = (const float*)d_in[3];
    const float* upb = (const float*)d_in[4];
    const float* dW  = (const float*)d_in[5];
    const float* db  = (const float*)d_in[6];
    float* out = (float*)d_out;

    float* gate_out = nullptr;
    if (out_size >= N_TOK * DM + N_TOK * NE)
        gate_out = out + (size_t)out_size - (size_t)N_TOK * NE;

    cudaFuncSetAttribute(gemm_kernel<true>,  cudaFuncAttributeMaxDynamicSharedMemorySize, SMEM_BYTES);
    cudaFuncSetAttribute(gemm_kernel<false>, cudaFuncAttributeMaxDynamicSharedMemorySize, SMEM_BYTES);

    init_kernel<<<1, 32>>>();
    gate_kernel<<<N_TOK / 8, 256>>>(x, gW, gb, gate_out);
    scan_kernel<<<1, 1>>>();
    scatter_kernel<<<N_TOK / 256, 256>>>();
    conv_x_kernel<<<N_TOK, 256>>>(x);

    dim3 b32(32, 8);
    conv_w_kernel<true><<<dim3(DF / 32, DM / 32, NE), b32>>>(upW, DM, DF);
    conv_w_kernel<false><<<dim3(DM / 32, DF / 32, NE), b32>>>(dW, DF, DM);

    gemm_kernel<true><<<dim3(DF / 256, MAX_TILES), 512, SMEM_BYTES>>>(upb, nullptr);
    gemm_kernel<false><<<dim3(DM / 256, MAX_TILES), 512, SMEM_BYTES>>>(db, out);
}

// round 8
// speedup vs baseline: 2.2274x; 1.4706x over previous
#include <cuda_runtime.h>
#include <cuda_fp16.h>
#include <cstdint>

#define N_TOK 8192
#define DM    1024
#define DF    4096
#define NE    8
#define MAX_TILES 71   // worst case: 64 + 7 partial tiles (128-row tiles)

// ---------------- scratch (static device, no allocations) ----------------
__device__ int   g_expert[N_TOK];
__device__ int   g_counts[NE];
__device__ int   g_offsets[NE + 1];
__device__ int   g_cursors[NE];
__device__ int   g_perm[N_TOK];
__device__ int   g_tile_prefix[NE + 1];

__device__ __half g_x16[(size_t)N_TOK * DM];    // gathered x, fp16
__device__ __half g_uw[(size_t)NE * DF * DM];   // up W^T  [e][n=DF][k=DM], fp16
__device__ __half g_dw[(size_t)NE * DM * DF];   // down W^T [e][n=DM][k=DF], fp16
__device__ __half g_h16[(size_t)N_TOK * DF];    // hidden, fp16

// ---------------- PTX helpers (baseline ISA only) ----------------
__device__ __forceinline__ uint32_t smem_u32(const void* p) {
    uint32_t a;
    asm("{ .reg .u64 t; cvta.to.shared.u64 t, %1; cvt.u32.u64 %0, t; }" : "=r"(a) : "l"(p));
    return a;
}
__device__ __forceinline__ void cp_async16(uint32_t dst, const void* src) {
    asm volatile("cp.async.cg.shared.global [%0], [%1], 16;"
                 :: "r"(dst), "l"(__cvta_generic_to_global(src)));
}
__device__ __forceinline__ void cp_commit() {
    asm volatile("cp.async.commit_group;");
}
template <int N>
__device__ __forceinline__ void cp_wait() {
    asm volatile("cp.async.wait_group %0;" :: "n"(N));
}
#define LDSM4(r0, r1, r2, r3, addr)                                            \
    asm volatile("ldmatrix.sync.aligned.m8n8.x4.shared.b16 {%0,%1,%2,%3}, [%4];" \
                 : "=r"(r0), "=r"(r1), "=r"(r2), "=r"(r3) : "r"(addr))
#define MMA16816(c, a0, a1, a2, a3, b0, b1)                                    \
    asm volatile("mma.sync.aligned.m16n8k16.row.col.f32.f16.f16.f32 "          \
                 "{%0,%1,%2,%3},{%4,%5,%6,%7},{%8,%9},{%0,%1,%2,%3};"          \
                 : "+f"((c)[0]), "+f"((c)[1]), "+f"((c)[2]), "+f"((c)[3])      \
                 : "r"(a0), "r"(a1), "r"(a2), "r"(a3), "r"(b0), "r"(b1))

// ---------------- routing kernels ----------------
__global__ void init_kernel() {
    int t = threadIdx.x;
    if (t < NE) { g_counts[t] = 0; g_cursors[t] = 0; }
}

__global__ void gate_kernel(const float* __restrict__ x,
                            const float* __restrict__ gW,
                            const float* __restrict__ gb,
                            float* gate_out) {
    int tok  = (blockIdx.x * blockDim.x + threadIdx.x) >> 5;
    int lane = threadIdx.x & 31;
    if (tok >= N_TOK) return;
    const float* xr = x + (size_t)tok * DM;
    float acc[NE];
#pragma unroll
    for (int e = 0; e < NE; e++) acc[e] = 0.f;
    for (int k = lane; k < DM; k += 32) {
        float xv = xr[k];
        const float* w = gW + k * NE;
#pragma unroll
        for (int e = 0; e < NE; e++) acc[e] += xv * w[e];
    }
#pragma unroll
    for (int e = 0; e < NE; e++) {
#pragma unroll
        for (int o = 16; o; o >>= 1) acc[e] += __shfl_xor_sync(0xffffffffu, acc[e], o);
        acc[e] += gb[e];
    }
    int best = 0;
#pragma unroll
    for (int e = 1; e < NE; e++) if (acc[e] > acc[best]) best = e;
    if (lane == 0) {
        g_expert[tok] = best;
        atomicAdd(&g_counts[best], 1);
    }
    if (gate_out && lane < NE)
        gate_out[(size_t)tok * NE + lane] = (lane == best) ? 1.0f : 0.0f;
}

__global__ void scan_kernel() {
    int s = 0, tp = 0;
    for (int e = 0; e < NE; e++) {
        g_offsets[e] = s;
        g_tile_prefix[e] = tp;
        tp += (g_counts[e] + 127) >> 7;
        s += g_counts[e];
    }
    g_offsets[NE] = s;
    g_tile_prefix[NE] = tp;
}

__global__ void scatter_kernel() {
    int t = blockIdx.x * blockDim.x + threadIdx.x;
    if (t >= N_TOK) return;
    int e = g_expert[t];
    int pos = g_offsets[e] + atomicAdd(&g_cursors[e], 1);
    g_perm[pos] = t;
}

// ---------------- conversions ----------------
__global__ void conv_x_kernel(const float* __restrict__ x) {
    int p = blockIdx.x;
    int t = threadIdx.x;
    int tok = g_perm[p];
    float4 v = ((const float4*)(x + (size_t)tok * DM))[t];
    __half2* d = (__half2*)(g_x16 + (size_t)p * DM);
    d[2 * t]     = __half2(__float2half(v.x), __float2half(v.y));
    d[2 * t + 1] = __half2(__float2half(v.z), __float2half(v.w));
}

// W: [e][K][N] fp32  ->  T: [e][N][K] fp16
template <bool UP>
__global__ void conv_w_kernel(const float* __restrict__ W, int K, int N) {
    __shared__ float tile[32][33];
    __half* T = UP ? g_uw : g_dw;
    int e  = blockIdx.z;
    int n0 = blockIdx.x * 32;
    int k0 = blockIdx.y * 32;
    int tx = threadIdx.x, ty = threadIdx.y;
    const float* Wp = W + (size_t)e * K * N;
#pragma unroll
    for (int i = 0; i < 4; i++)
        tile[ty + i * 8][tx] = Wp[(size_t)(k0 + ty + i * 8) * N + n0 + tx];
    __syncthreads();
    size_t base = (size_t)e * N * K;
#pragma unroll
    for (int i = 0; i < 4; i++) {
        float v = tile[tx][ty + i * 8];
        T[base + (size_t)(n0 + ty + i * 8) * K + k0 + tx] = __float2half(v);
    }
}

// ---------------- HMMA grouped GEMM (full fp16, 1 product) ----------------
// CTA tile 128(M) x 256(N) x 64(K-chunk). 512 threads, 16 warps (4m x 4n), warp tile 32x64.
// SMEM stage: A(128) + B(256) rows x 144B (128B data + 16B pad) = 55296 B.
// 3-stage pipeline, cp.async.wait_group 1 -> one full stage always in flight.
#define ROW_B    144
#define OFF_A    0
#define OFF_B    (128 * ROW_B)            // 18432
#define STAGE_B  (OFF_B + 256 * ROW_B)    // 55296
#define NSTAGE   3
#define SMEM_BYTES (NSTAGE * STAGE_B)     // 165888

template <bool IS_UP>
__global__ void __launch_bounds__(512, 1)
gemm_kernel(const float* __restrict__ bias, float* __restrict__ out) {
    constexpr int K   = IS_UP ? DM : DF;
    constexpr int NT  = IS_UP ? DF : DM;
    constexpr int NCH = K / 64;

    int ty = blockIdx.y;
    if (ty >= g_tile_prefix[NE]) return;
    int e = 0;
    while (ty >= g_tile_prefix[e + 1]) e++;
    int off = g_offsets[e];
    int cnt = g_offsets[e + 1] - off;
    int m0  = (ty - g_tile_prefix[e]) * 128;
    int n0  = blockIdx.x * 256;
    int valid = cnt - m0; if (valid > 128) valid = 128;

    extern __shared__ char smem[];
    uint32_t sb = smem_u32(smem);

    int tid = threadIdx.x, lane = tid & 31, wid = tid >> 5;
    int wm = (wid & 3) * 32;        // 0,32,64,96
    int wn = (wid >> 2) * 64;       // 0,64,128,192
    int g = lane >> 2, t4 = lane & 3;

    const __half* Ap = (IS_UP ? g_x16 : g_h16) + (size_t)(off + m0) * K;
    const __half* Bp = (IS_UP ? g_uw  : g_dw)  + ((size_t)e * NT + n0) * K;

    float acc[2][8][4];
#pragma unroll
    for (int i = 0; i < 2; i++)
#pragma unroll
        for (int j = 0; j < 8; j++)
#pragma unroll
            for (int r = 0; r < 4; r++) acc[i][j][r] = 0.f;

    // loader: stage = 384 rows x 128B = 3072 x 16B chunks, 6 per thread.
    auto load_chunk = [&](int c, int st) {
        int r0  = tid >> 3;            // 0..63
        int seg = tid & 7;             // 0..7
        uint32_t dstb = sb + st * STAGE_B + seg * 16;
        int col = c * 64 + seg * 8;
#pragma unroll
        for (int i = 0; i < 6; i++) {
            if (i < 2) {
                int lrow = r0 + (i & 1) * 64;          // A rows 0..127
                int ra = (lrow < valid) ? lrow : 0;    // dup-safe clamp
                cp_async16(dstb + OFF_A + (uint32_t)lrow * ROW_B, Ap + (size_t)ra * K + col);
            } else {
                int lrow = r0 + ((i - 2) & 3) * 64;    // B rows 0..255
                cp_async16(dstb + OFF_B + (uint32_t)lrow * ROW_B, Bp + (size_t)lrow * K + col);
            }
        }
    };

    load_chunk(0, 0); cp_commit();
    load_chunk(1, 1); cp_commit();

    for (int c = 0; c < NCH; c++) {
        cp_wait<1>();
        __syncthreads();
        if (c + 2 < NCH) load_chunk(c + 2, (c + 2) % NSTAGE);
        cp_commit();   // empty groups at tail keep FIFO count aligned

        uint32_t stb = sb + (c % NSTAGE) * STAGE_B;
#pragma unroll
        for (int kk = 0; kk < 4; kk++) {
            uint32_t kb = kk * 32;
            uint32_t af[2][4];
#pragma unroll
            for (int mi = 0; mi < 2; mi++) {
                uint32_t rb = stb + OFF_A
                            + (uint32_t)(wm + mi * 16 + (lane & 15)) * ROW_B
                            + kb + ((lane >> 4) & 1) * 16;
                LDSM4(af[mi][0], af[mi][1], af[mi][2], af[mi][3], rb);
            }
            uint32_t bf[8][2];
#pragma unroll
            for (int p = 0; p < 4; p++) {
                uint32_t rb = stb + OFF_B
                            + (uint32_t)(wn + p * 16 + ((lane >> 4) & 1) * 8 + (lane & 7)) * ROW_B
                            + kb + ((lane >> 3) & 1) * 16;
                LDSM4(bf[2 * p][0], bf[2 * p][1], bf[2 * p + 1][0], bf[2 * p + 1][1], rb);
            }
#pragma unroll
            for (int mi = 0; mi < 2; mi++)
#pragma unroll
                for (int ni = 0; ni < 8; ni++)
                    MMA16816(acc[mi][ni], af[mi][0], af[mi][1], af[mi][2], af[mi][3],
                             bf[ni][0], bf[ni][1]);
        }
    }

    // ---------------- epilogue (direct global stores) ----------------
    const float* bptr = bias + (size_t)e * NT + n0;
#pragma unroll
    for (int mi = 0; mi < 2; mi++) {
#pragma unroll
        for (int rr = 0; rr < 2; rr++) {
            int m = wm + mi * 16 + g + rr * 8;
            if (m >= valid) continue;
            if (IS_UP) {
                size_t pos = (size_t)(off + m0 + m);
                __half* hrow = g_h16 + pos * DF + n0;
#pragma unroll
                for (int ni = 0; ni < 8; ni++) {
                    int bn = wn + ni * 8 + 2 * t4;
                    float v0 = acc[mi][ni][rr * 2 + 0] + bptr[bn];
                    float v1 = acc[mi][ni][rr * 2 + 1] + bptr[bn + 1];
                    v0 = v0 > 0.f ? v0 : 0.f;
                    v1 = v1 > 0.f ? v1 : 0.f;
                    *(__half2*)(hrow + bn) = __half2(__float2half(v0), __float2half(v1));
                }
            } else {
                int tok = g_perm[off + m0 + m];
                float* orow = out + (size_t)tok * DM + n0;
#pragma unroll
                for (int ni = 0; ni < 8; ni++) {
                    int bn = wn + ni * 8 + 2 * t4;
                    float2 v;
                    v.x = acc[mi][ni][rr * 2 + 0] + bptr[bn];
                    v.y = acc[mi][ni][rr * 2 + 1] + bptr[bn + 1];
                    *(float2*)(orow + bn) = v;
                }
            }
        }
    }
}

// ---------------- launch ----------------
extern "C" void kernel_launch(void* const* d_in, const int* in_sizes, int n_in,
                              void* d_out, int out_size) {
    const float* x   = (const float*)d_in[0];
    const float* gW  = (const float*)d_in[1];
    const float* gb  = (const float*)d_in[2];
    const float* upW = (const float*)d_in[3];
    const float* upb = (const float*)d_in[4];
    const float* dW  = (const float*)d_in[5];
    const float* db  = (const float*)d_in[6];
    float* out = (float*)d_out;

    float* gate_out = nullptr;
    if (out_size >= N_TOK * DM + N_TOK * NE)
        gate_out = out + (size_t)out_size - (size_t)N_TOK * NE;

    cudaFuncSetAttribute(gemm_kernel<true>,  cudaFuncAttributeMaxDynamicSharedMemorySize, SMEM_BYTES);
    cudaFuncSetAttribute(gemm_kernel<false>, cudaFuncAttributeMaxDynamicSharedMemorySize, SMEM_BYTES);

    init_kernel<<<1, 32>>>();
    gate_kernel<<<N_TOK / 8, 256>>>(x, gW, gb, gate_out);
    scan_kernel<<<1, 1>>>();
    scatter_kernel<<<N_TOK / 256, 256>>>();
    conv_x_kernel<<<N_TOK, 256>>>(x);

    dim3 b32(32, 8);
    conv_w_kernel<true><<<dim3(DF / 32, DM / 32, NE), b32>>>(upW, DM, DF);
    conv_w_kernel<false><<<dim3(DM / 32, DF / 32, NE), b32>>>(dW, DF, DM);

    gemm_kernel<true><<<dim3(DF / 256, MAX_TILES), 512, SMEM_BYTES>>>(upb, nullptr);
    gemm_kernel<false><<<dim3(DM / 256, MAX_TILES), 512, SMEM_BYTES>>>(db, out);
}

// round 9
// speedup vs baseline: 2.4001x; 1.0775x over previous
#include <cuda_runtime.h>
#include <cuda_fp16.h>
#include <cstdint>

#define N_TOK 8192
#define DM    1024
#define DF    4096
#define NE    8
#define MAX_TILES 71   // worst case: 64 + 7 partial tiles (128-row tiles)

// ---------------- scratch (static device, no allocations) ----------------
__device__ int   g_expert[N_TOK];
__device__ int   g_counts[NE];
__device__ int   g_offsets[NE + 1];
__device__ int   g_cursors[NE];
__device__ int   g_perm[N_TOK];
__device__ int   g_tile_prefix[NE + 1];

__device__ __half g_x16[(size_t)N_TOK * DM];    // gathered x, fp16
__device__ __half g_uw[(size_t)NE * DM * DF];   // up W, fp16, ORIGINAL [e][k=DM][n=DF]
__device__ __half g_dw[(size_t)NE * DF * DM];   // down W, fp16, ORIGINAL [e][k=DF][n=DM]
__device__ __half g_h16[(size_t)N_TOK * DF];    // hidden, fp16

// ---------------- PTX helpers (baseline ISA only) ----------------
__device__ __forceinline__ uint32_t smem_u32(const void* p) {
    uint32_t a;
    asm("{ .reg .u64 t; cvta.to.shared.u64 t, %1; cvt.u32.u64 %0, t; }" : "=r"(a) : "l"(p));
    return a;
}
__device__ __forceinline__ void cp_async16(uint32_t dst, const void* src) {
    asm volatile("cp.async.cg.shared.global [%0], [%1], 16;"
                 :: "r"(dst), "l"(__cvta_generic_to_global(src)));
}
__device__ __forceinline__ void cp_commit() {
    asm volatile("cp.async.commit_group;");
}
template <int N>
__device__ __forceinline__ void cp_wait() {
    asm volatile("cp.async.wait_group %0;" :: "n"(N));
}
#define LDSM4(r0, r1, r2, r3, addr)                                            \
    asm volatile("ldmatrix.sync.aligned.m8n8.x4.shared.b16 {%0,%1,%2,%3}, [%4];" \
                 : "=r"(r0), "=r"(r1), "=r"(r2), "=r"(r3) : "r"(addr))
#define LDSM4T(r0, r1, r2, r3, addr)                                           \
    asm volatile("ldmatrix.sync.aligned.m8n8.x4.trans.shared.b16 {%0,%1,%2,%3}, [%4];" \
                 : "=r"(r0), "=r"(r1), "=r"(r2), "=r"(r3) : "r"(addr))
#define MMA16816(c, a0, a1, a2, a3, b0, b1)                                    \
    asm volatile("mma.sync.aligned.m16n8k16.row.col.f32.f16.f16.f32 "          \
                 "{%0,%1,%2,%3},{%4,%5,%6,%7},{%8,%9},{%0,%1,%2,%3};"          \
                 : "+f"((c)[0]), "+f"((c)[1]), "+f"((c)[2]), "+f"((c)[3])      \
                 : "r"(a0), "r"(a1), "r"(a2), "r"(a3), "r"(b0), "r"(b1))

// ---------------- routing kernels ----------------
__global__ void init_kernel() {
    int t = threadIdx.x;
    if (t < NE) { g_counts[t] = 0; g_cursors[t] = 0; }
}

__global__ void gate_kernel(const float* __restrict__ x,
                            const float* __restrict__ gW,
                            const float* __restrict__ gb,
                            float* gate_out) {
    int tok  = (blockIdx.x * blockDim.x + threadIdx.x) >> 5;
    int lane = threadIdx.x & 31;
    if (tok >= N_TOK) return;
    const float* xr = x + (size_t)tok * DM;
    float acc[NE];
#pragma unroll
    for (int e = 0; e < NE; e++) acc[e] = 0.f;
    for (int k = lane; k < DM; k += 32) {
        float xv = xr[k];
        const float* w = gW + k * NE;
#pragma unroll
        for (int e = 0; e < NE; e++) acc[e] += xv * w[e];
    }
#pragma unroll
    for (int e = 0; e < NE; e++) {
#pragma unroll
        for (int o = 16; o; o >>= 1) acc[e] += __shfl_xor_sync(0xffffffffu, acc[e], o);
        acc[e] += gb[e];
    }
    int best = 0;
#pragma unroll
    for (int e = 1; e < NE; e++) if (acc[e] > acc[best]) best = e;
    if (lane == 0) {
        g_expert[tok] = best;
        atomicAdd(&g_counts[best], 1);
    }
    if (gate_out && lane < NE)
        gate_out[(size_t)tok * NE + lane] = (lane == best) ? 1.0f : 0.0f;
}

__global__ void scan_kernel() {
    int s = 0, tp = 0;
    for (int e = 0; e < NE; e++) {
        g_offsets[e] = s;
        g_tile_prefix[e] = tp;
        tp += (g_counts[e] + 127) >> 7;
        s += g_counts[e];
    }
    g_offsets[NE] = s;
    g_tile_prefix[NE] = tp;
}

__global__ void scatter_kernel() {
    int t = blockIdx.x * blockDim.x + threadIdx.x;
    if (t >= N_TOK) return;
    int e = g_expert[t];
    int pos = g_offsets[e] + atomicAdd(&g_cursors[e], 1);
    g_perm[pos] = t;
}

// ---------------- conversions ----------------
__global__ void conv_x_kernel(const float* __restrict__ x) {
    int p = blockIdx.x;
    int t = threadIdx.x;
    int tok = g_perm[p];
    float4 v = ((const float4*)(x + (size_t)tok * DM))[t];
    __half2* d = (__half2*)(g_x16 + (size_t)p * DM);
    d[2 * t]     = __half2(__float2half(v.x), __float2half(v.y));
    d[2 * t + 1] = __half2(__float2half(v.z), __float2half(v.w));
}

// Both weights fp32 -> fp16, SAME layout (pure streaming convert, no transpose)
__global__ void conv_w_all(const float* __restrict__ upW, const float* __restrict__ dW) {
    const size_t N4 = (size_t)NE * DM * DF / 4;   // 8388608 float4s per tensor
    size_t j = (size_t)blockIdx.x * blockDim.x + threadIdx.x;
    if (j < N4) {
        float4 v = ((const float4*)upW)[j];
        ((__half2*)g_uw)[2 * j]     = __half2(__float2half(v.x), __float2half(v.y));
        ((__half2*)g_uw)[2 * j + 1] = __half2(__float2half(v.z), __float2half(v.w));
    } else {
        size_t k = j - N4;
        float4 v = ((const float4*)dW)[k];
        ((__half2*)g_dw)[2 * k]     = __half2(__float2half(v.x), __float2half(v.y));
        ((__half2*)g_dw)[2 * k + 1] = __half2(__float2half(v.z), __float2half(v.w));
    }
}

// ---------------- HMMA grouped GEMM (full fp16, row-major B via ldmatrix.trans) ----------------
// CTA tile 128(M) x 256(N) x 64(K-chunk). 512 threads, 16 warps (4m x 4n), warp tile 32x64.
// SMEM stage: A 128 rows x 144B ([m][k]) + B 64 k-rows x 528B ([k][n], 512B data + 16B pad).
// 3-stage pipeline, cp.async.wait_group 1.
#define ROW_A    144
#define ROW_BB   528
#define OFF_A    0
#define OFF_B    (128 * ROW_A)            // 18432
#define STAGE_B  (OFF_B + 64 * ROW_BB)    // 52224
#define NSTAGE   3
#define SMEM_BYTES (NSTAGE * STAGE_B)     // 156672

template <bool IS_UP>
__global__ void __launch_bounds__(512, 1)
gemm_kernel(const float* __restrict__ bias, float* __restrict__ out) {
    constexpr int K   = IS_UP ? DM : DF;
    constexpr int NT  = IS_UP ? DF : DM;
    constexpr int NCH = K / 64;

    int ty = blockIdx.y;
    if (ty >= g_tile_prefix[NE]) return;
    int e = 0;
    while (ty >= g_tile_prefix[e + 1]) e++;
    int off = g_offsets[e];
    int cnt = g_offsets[e + 1] - off;
    int m0  = (ty - g_tile_prefix[e]) * 128;
    int n0  = blockIdx.x * 256;
    int valid = cnt - m0; if (valid > 128) valid = 128;

    extern __shared__ char smem[];
    uint32_t sb = smem_u32(smem);

    int tid = threadIdx.x, lane = tid & 31, wid = tid >> 5;
    int wm = (wid & 3) * 32;        // 0,32,64,96
    int wn = (wid >> 2) * 64;       // 0,64,128,192
    int g = lane >> 2, t4 = lane & 3;

    const __half* Ap = (IS_UP ? g_x16 : g_h16) + (size_t)(off + m0) * K;
    // B in original [k][n] layout; fold expert and n0 offsets in
    const __half* Bp = (IS_UP ? g_uw : g_dw) + (size_t)e * K * NT + n0;

    float acc[2][8][4];
#pragma unroll
    for (int i = 0; i < 2; i++)
#pragma unroll
        for (int j = 0; j < 8; j++)
#pragma unroll
            for (int r = 0; r < 4; r++) acc[i][j][r] = 0.f;

    // loader: A = 1024 chunks (128 rows x 8 segs), B = 2048 chunks (64 k-rows x 32 segs); 6/thread
    auto load_chunk = [&](int c, int st) {
        uint32_t stb = sb + st * STAGE_B;
#pragma unroll
        for (int i = 0; i < 2; i++) {
            int idx = tid + i * 512;           // 0..1023
            int row = idx >> 3, seg = idx & 7;
            int ra = (row < valid) ? row : 0;  // dup-safe clamp
            cp_async16(stb + OFF_A + (uint32_t)row * ROW_A + seg * 16,
                       Ap + (size_t)ra * K + c * 64 + seg * 8);
        }
#pragma unroll
        for (int i = 0; i < 4; i++) {
            int idx = tid + i * 512;           // 0..2047
            int krow = idx >> 5, seg = idx & 31;
            cp_async16(stb + OFF_B + (uint32_t)krow * ROW_BB + seg * 16,
                       Bp + (size_t)(c * 64 + krow) * NT + seg * 8);
        }
    };

    load_chunk(0, 0); cp_commit();
    load_chunk(1, 1); cp_commit();

    for (int c = 0; c < NCH; c++) {
        cp_wait<1>();
        __syncthreads();
        if (c + 2 < NCH) load_chunk(c + 2, (c + 2) % NSTAGE);
        cp_commit();   // empty groups at tail keep FIFO count aligned

        uint32_t stb = sb + (c % NSTAGE) * STAGE_B;
#pragma unroll
        for (int kk = 0; kk < 4; kk++) {
            // A fragments ([m][k] row-major, non-trans)
            uint32_t af[2][4];
#pragma unroll
            for (int mi = 0; mi < 2; mi++) {
                uint32_t rb = stb + OFF_A
                            + (uint32_t)(wm + mi * 16 + (lane & 15)) * ROW_A
                            + kk * 32 + ((lane >> 4) & 1) * 16;
                LDSM4(af[mi][0], af[mi][1], af[mi][2], af[mi][3], rb);
            }
            // B fragments ([k][n] row-major, trans): x4 covers k16 x n16
            uint32_t bf[8][2];
#pragma unroll
            for (int p = 0; p < 4; p++) {
                uint32_t rb = stb + OFF_B
                            + (uint32_t)(kk * 16 + (lane & 15)) * ROW_BB
                            + (uint32_t)(wn + p * 16 + ((lane >> 4) & 1) * 8) * 2;
                LDSM4T(bf[2 * p][0], bf[2 * p][1], bf[2 * p + 1][0], bf[2 * p + 1][1], rb);
            }
#pragma unroll
            for (int mi = 0; mi < 2; mi++)
#pragma unroll
                for (int ni = 0; ni < 8; ni++)
                    MMA16816(acc[mi][ni], af[mi][0], af[mi][1], af[mi][2], af[mi][3],
                             bf[ni][0], bf[ni][1]);
        }
    }

    // ---------------- epilogue (direct global stores) ----------------
    const float* bptr = bias + (size_t)e * NT + n0;
#pragma unroll
    for (int mi = 0; mi < 2; mi++) {
#pragma unroll
        for (int rr = 0; rr < 2; rr++) {
            int m = wm + mi * 16 + g + rr * 8;
            if (m >= valid) continue;
            if (IS_UP) {
                size_t pos = (size_t)(off + m0 + m);
                __half* hrow = g_h16 + pos * DF + n0;
#pragma unroll
                for (int ni = 0; ni < 8; ni++) {
                    int bn = wn + ni * 8 + 2 * t4;
                    float v0 = acc[mi][ni][rr * 2 + 0] + bptr[bn];
                    float v1 = acc[mi][ni][rr * 2 + 1] + bptr[bn + 1];
                    v0 = v0 > 0.f ? v0 : 0.f;
                    v1 = v1 > 0.f ? v1 : 0.f;
                    *(__half2*)(hrow + bn) = __half2(__float2half(v0), __float2half(v1));
                }
            } else {
                int tok = g_perm[off + m0 + m];
                float* orow = out + (size_t)tok * DM + n0;
#pragma unroll
                for (int ni = 0; ni < 8; ni++) {
                    int bn = wn + ni * 8 + 2 * t4;
                    float2 v;
                    v.x = acc[mi][ni][rr * 2 + 0] + bptr[bn];
                    v.y = acc[mi][ni][rr * 2 + 1] + bptr[bn + 1];
                    *(float2*)(orow + bn) = v;
                }
            }
        }
    }
}

// ---------------- launch ----------------
extern "C" void kernel_launch(void* const* d_in, const int* in_sizes, int n_in,
                              void* d_out, int out_size) {
    const float* x   = (const float*)d_in[0];
    const float* gW  = (const float*)d_in[1];
    const float* gb  = (const float*)d_in[2];
    const float* upW = (const float*)d_in[3];
    const float* upb = (const float*)d_in[4];
    const float* dW  = (const float*)d_in[5];
    const float* db  = (const float*)d_in[6];
    float* out = (float*)d_out;

    float* gate_out = nullptr;
    if (out_size >= N_TOK * DM + N_TOK * NE)
        gate_out = out + (size_t)out_size - (size_t)N_TOK * NE;

    cudaFuncSetAttribute(gemm_kernel<true>,  cudaFuncAttributeMaxDynamicSharedMemorySize, SMEM_BYTES);
    cudaFuncSetAttribute(gemm_kernel<false>, cudaFuncAttributeMaxDynamicSharedMemorySize, SMEM_BYTES);

    init_kernel<<<1, 32>>>();
    gate_kernel<<<N_TOK / 8, 256>>>(x, gW, gb, gate_out);
    scan_kernel<<<1, 1>>>();
    scatter_kernel<<<N_TOK / 256, 256>>>();
    conv_x_kernel<<<N_TOK, 256>>>(x);

    // fused streaming weight convert: 2 * 8388608 float4s, 256 thr/block
    conv_w_all<<<65536, 256>>>(upW, dW);

    gemm_kernel<true><<<dim3(DF / 256, MAX_TILES), 512, SMEM_BYTES>>>(upb, nullptr);
    gemm_kernel<false><<<dim3(DM / 256, MAX_TILES), 512, SMEM_BYTES>>>(db, out);
}

// round 10
// speedup vs baseline: 2.4490x; 1.0204x over previous
#include <cuda_runtime.h>
#include <cuda_fp16.h>
#include <cstdint>

#define N_TOK 8192
#define DM    1024
#define DF    4096
#define NE    8
#define MAX_TILES 71   // worst case: 64 + 7 partial tiles (128-row tiles)

// ---------------- scratch (static device, no allocations) ----------------
__device__ int   g_expert[N_TOK];
__device__ int   g_counts[NE];
__device__ int   g_offsets[NE + 1];
__device__ int   g_cursors[NE];
__device__ int   g_perm[N_TOK];
__device__ int   g_tile_prefix[NE + 1];

__device__ __half g_x16[(size_t)N_TOK * DM];    // gathered x, fp16
__device__ __half g_uw[(size_t)NE * DM * DF];   // up W, fp16, ORIGINAL [e][k=DM][n=DF]
__device__ __half g_dw[(size_t)NE * DF * DM];   // down W, fp16, ORIGINAL [e][k=DF][n=DM]
__device__ __half g_h16[(size_t)N_TOK * DF];    // hidden, fp16

// ---------------- PTX helpers (baseline ISA only) ----------------
__device__ __forceinline__ uint32_t smem_u32(const void* p) {
    uint32_t a;
    asm("{ .reg .u64 t; cvta.to.shared.u64 t, %1; cvt.u32.u64 %0, t; }" : "=r"(a) : "l"(p));
    return a;
}
__device__ __forceinline__ void cp_async16(uint32_t dst, const void* src) {
    asm volatile("cp.async.cg.shared.global [%0], [%1], 16;"
                 :: "r"(dst), "l"(__cvta_generic_to_global(src)));
}
__device__ __forceinline__ void cp_commit() {
    asm volatile("cp.async.commit_group;");
}
template <int N>
__device__ __forceinline__ void cp_wait() {
    asm volatile("cp.async.wait_group %0;" :: "n"(N));
}
#define LDSM4(r0, r1, r2, r3, addr)                                            \
    asm volatile("ldmatrix.sync.aligned.m8n8.x4.shared.b16 {%0,%1,%2,%3}, [%4];" \
                 : "=r"(r0), "=r"(r1), "=r"(r2), "=r"(r3) : "r"(addr))
#define LDSM4T(r0, r1, r2, r3, addr)                                           \
    asm volatile("ldmatrix.sync.aligned.m8n8.x4.trans.shared.b16 {%0,%1,%2,%3}, [%4];" \
                 : "=r"(r0), "=r"(r1), "=r"(r2), "=r"(r3) : "r"(addr))
#define MMA16816(c, a0, a1, a2, a3, b0, b1)                                    \
    asm volatile("mma.sync.aligned.m16n8k16.row.col.f32.f16.f16.f32 "          \
                 "{%0,%1,%2,%3},{%4,%5,%6,%7},{%8,%9},{%0,%1,%2,%3};"          \
                 : "+f"((c)[0]), "+f"((c)[1]), "+f"((c)[2]), "+f"((c)[3])      \
                 : "r"(a0), "r"(a1), "r"(a2), "r"(a3), "r"(b0), "r"(b1))

// ---------------- routing kernels ----------------
__global__ void init_kernel() {
    int t = threadIdx.x;
    if (t < NE) { g_counts[t] = 0; g_cursors[t] = 0; }
}

__global__ void gate_kernel(const float* __restrict__ x,
                            const float* __restrict__ gW,
                            const float* __restrict__ gb,
                            float* gate_out) {
    int tok  = (blockIdx.x * blockDim.x + threadIdx.x) >> 5;
    int lane = threadIdx.x & 31;
    if (tok >= N_TOK) return;
    const float* xr = x + (size_t)tok * DM;
    float acc[NE];
#pragma unroll
    for (int e = 0; e < NE; e++) acc[e] = 0.f;
    for (int k = lane; k < DM; k += 32) {
        float xv = xr[k];
        const float* w = gW + k * NE;
#pragma unroll
        for (int e = 0; e < NE; e++) acc[e] += xv * w[e];
    }
#pragma unroll
    for (int e = 0; e < NE; e++) {
#pragma unroll
        for (int o = 16; o; o >>= 1) acc[e] += __shfl_xor_sync(0xffffffffu, acc[e], o);
        acc[e] += gb[e];
    }
    int best = 0;
#pragma unroll
    for (int e = 1; e < NE; e++) if (acc[e] > acc[best]) best = e;
    if (lane == 0) {
        g_expert[tok] = best;
        atomicAdd(&g_counts[best], 1);
    }
    if (gate_out && lane < NE)
        gate_out[(size_t)tok * NE + lane] = (lane == best) ? 1.0f : 0.0f;
}

__global__ void scan_kernel() {
    int s = 0, tp = 0;
    for (int e = 0; e < NE; e++) {
        g_offsets[e] = s;
        g_tile_prefix[e] = tp;
        tp += (g_counts[e] + 127) >> 7;
        s += g_counts[e];
    }
    g_offsets[NE] = s;
    g_tile_prefix[NE] = tp;
}

__global__ void scatter_kernel() {
    int t = blockIdx.x * blockDim.x + threadIdx.x;
    if (t >= N_TOK) return;
    int e = g_expert[t];
    int pos = g_offsets[e] + atomicAdd(&g_cursors[e], 1);
    g_perm[pos] = t;
}

// ---------------- conversions ----------------
__global__ void conv_x_kernel(const float* __restrict__ x) {
    int p = blockIdx.x;
    int t = threadIdx.x;
    int tok = g_perm[p];
    float4 v = ((const float4*)(x + (size_t)tok * DM))[t];
    __half2* d = (__half2*)(g_x16 + (size_t)p * DM);
    d[2 * t]     = __half2(__float2half(v.x), __float2half(v.y));
    d[2 * t + 1] = __half2(__float2half(v.z), __float2half(v.w));
}

// streaming fp32 -> fp16 convert, same layout (no transpose)
__global__ void conv_w_one(const float* __restrict__ W, __half* __restrict__ T) {
    size_t j = (size_t)blockIdx.x * blockDim.x + threadIdx.x;   // one float4 per thread
    float4 v = ((const float4*)W)[j];
    ((__half2*)T)[2 * j]     = __half2(__float2half(v.x), __float2half(v.y));
    ((__half2*)T)[2 * j + 1] = __half2(__float2half(v.z), __float2half(v.w));
}

// ---------------- HMMA grouped GEMM (full fp16, row-major B via ldmatrix.trans) ----------------
// CTA tile 128(M) x 256(N) x 64(K-chunk). 512 threads, 16 warps (4m x 4n), warp tile 32x64.
// SMEM stage: A 128 rows x 144B ([m][k]) + B 64 k-rows x 528B ([k][n], 512B data + 16B pad).
// 3-stage pipeline, cp.async.wait_group 1.
#define ROW_A    144
#define ROW_BB   528
#define OFF_A    0
#define OFF_B    (128 * ROW_A)            // 18432
#define STAGE_B  (OFF_B + 64 * ROW_BB)    // 52224
#define NSTAGE   3
#define SMEM_BYTES (NSTAGE * STAGE_B)     // 156672

template <bool IS_UP>
__global__ void __launch_bounds__(512, 1)
gemm_kernel(const float* __restrict__ bias, float* __restrict__ out) {
    constexpr int K   = IS_UP ? DM : DF;
    constexpr int NT  = IS_UP ? DF : DM;
    constexpr int NCH = K / 64;

    int ty = blockIdx.y;
    if (ty >= g_tile_prefix[NE]) return;
    int e = 0;
    while (ty >= g_tile_prefix[e + 1]) e++;
    int off = g_offsets[e];
    int cnt = g_offsets[e + 1] - off;
    int m0  = (ty - g_tile_prefix[e]) * 128;
    int n0  = blockIdx.x * 256;
    int valid = cnt - m0; if (valid > 128) valid = 128;

    extern __shared__ char smem[];
    uint32_t sb = smem_u32(smem);

    int tid = threadIdx.x, lane = tid & 31, wid = tid >> 5;
    int wm = (wid & 3) * 32;        // 0,32,64,96
    int wn = (wid >> 2) * 64;       // 0,64,128,192
    int g = lane >> 2, t4 = lane & 3;

    const __half* Ap = (IS_UP ? g_x16 : g_h16) + (size_t)(off + m0) * K;
    const __half* Bp = (IS_UP ? g_uw : g_dw) + (size_t)e * K * NT + n0;

    float acc[2][8][4];
#pragma unroll
    for (int i = 0; i < 2; i++)
#pragma unroll
        for (int j = 0; j < 8; j++)
#pragma unroll
            for (int r = 0; r < 4; r++) acc[i][j][r] = 0.f;

    // loader: A = 1024 chunks (128 rows x 8 segs), B = 2048 chunks (64 k-rows x 32 segs); 6/thread
    auto load_chunk = [&](int c, int st) {
        uint32_t stb = sb + st * STAGE_B;
#pragma unroll
        for (int i = 0; i < 2; i++) {
            int idx = tid + i * 512;           // 0..1023
            int row = idx >> 3, seg = idx & 7;
            int ra = (row < valid) ? row : 0;  // dup-safe clamp
            cp_async16(stb + OFF_A + (uint32_t)row * ROW_A + seg * 16,
                       Ap + (size_t)ra * K + c * 64 + seg * 8);
        }
#pragma unroll
        for (int i = 0; i < 4; i++) {
            int idx = tid + i * 512;           // 0..2047
            int krow = idx >> 5, seg = idx & 31;
            cp_async16(stb + OFF_B + (uint32_t)krow * ROW_BB + seg * 16,
                       Bp + (size_t)(c * 64 + krow) * NT + seg * 8);
        }
    };

    load_chunk(0, 0); cp_commit();
    load_chunk(1, 1); cp_commit();

    for (int c = 0; c < NCH; c++) {
        cp_wait<1>();
        __syncthreads();
        if (c + 2 < NCH) load_chunk(c + 2, (c + 2) % NSTAGE);
        cp_commit();   // empty groups at tail keep FIFO count aligned

        uint32_t stb = sb + (c % NSTAGE) * STAGE_B;
#pragma unroll
        for (int kk = 0; kk < 4; kk++) {
            // A fragments ([m][k] row-major, non-trans)
            uint32_t af[2][4];
#pragma unroll
            for (int mi = 0; mi < 2; mi++) {
                uint32_t rb = stb + OFF_A
                            + (uint32_t)(wm + mi * 16 + (lane & 15)) * ROW_A
                            + kk * 32 + ((lane >> 4) & 1) * 16;
                LDSM4(af[mi][0], af[mi][1], af[mi][2], af[mi][3], rb);
            }
            // B fragments ([k][n] row-major, trans): x4 covers k16 x n16
            uint32_t bf[8][2];
#pragma unroll
            for (int p = 0; p < 4; p++) {
                uint32_t rb = stb + OFF_B
                            + (uint32_t)(kk * 16 + (lane & 15)) * ROW_BB
                            + (uint32_t)(wn + p * 16 + ((lane >> 4) & 1) * 8) * 2;
                LDSM4T(bf[2 * p][0], bf[2 * p][1], bf[2 * p + 1][0], bf[2 * p + 1][1], rb);
            }
#pragma unroll
            for (int mi = 0; mi < 2; mi++)
#pragma unroll
                for (int ni = 0; ni < 8; ni++)
                    MMA16816(acc[mi][ni], af[mi][0], af[mi][1], af[mi][2], af[mi][3],
                             bf[ni][0], bf[ni][1]);
        }
    }

    // ---------------- epilogue (direct global stores) ----------------
    const float* bptr = bias + (size_t)e * NT + n0;
#pragma unroll
    for (int mi = 0; mi < 2; mi++) {
#pragma unroll
        for (int rr = 0; rr < 2; rr++) {
            int m = wm + mi * 16 + g + rr * 8;
            if (m >= valid) continue;
            if (IS_UP) {
                size_t pos = (size_t)(off + m0 + m);
                __half* hrow = g_h16 + pos * DF + n0;
#pragma unroll
                for (int ni = 0; ni < 8; ni++) {
                    int bn = wn + ni * 8 + 2 * t4;
                    float v0 = acc[mi][ni][rr * 2 + 0] + bptr[bn];
                    float v1 = acc[mi][ni][rr * 2 + 1] + bptr[bn + 1];
                    v0 = v0 > 0.f ? v0 : 0.f;
                    v1 = v1 > 0.f ? v1 : 0.f;
                    *(__half2*)(hrow + bn) = __half2(__float2half(v0), __float2half(v1));
                }
            } else {
                int tok = g_perm[off + m0 + m];
                float* orow = out + (size_t)tok * DM + n0;
#pragma unroll
                for (int ni = 0; ni < 8; ni++) {
                    int bn = wn + ni * 8 + 2 * t4;
                    float2 v;
                    v.x = acc[mi][ni][rr * 2 + 0] + bptr[bn];
                    v.y = acc[mi][ni][rr * 2 + 1] + bptr[bn + 1];
                    *(float2*)(orow + bn) = v;
                }
            }
        }
    }
}

// ---------------- launch ----------------
extern "C" void kernel_launch(void* const* d_in, const int* in_sizes, int n_in,
                              void* d_out, int out_size) {
    const float* x   = (const float*)d_in[0];
    const float* gW  = (const float*)d_in[1];
    const float* gb  = (const float*)d_in[2];
    const float* upW = (const float*)d_in[3];
    const float* upb = (const float*)d_in[4];
    const float* dW  = (const float*)d_in[5];
    const float* db  = (const float*)d_in[6];
    float* out = (float*)d_out;

    float* gate_out = nullptr;
    if (out_size >= N_TOK * DM + N_TOK * NE)
        gate_out = out + (size_t)out_size - (size_t)N_TOK * NE;

    cudaFuncSetAttribute(gemm_kernel<true>,  cudaFuncAttributeMaxDynamicSharedMemorySize, SMEM_BYTES);
    cudaFuncSetAttribute(gemm_kernel<false>, cudaFuncAttributeMaxDynamicSharedMemorySize, SMEM_BYTES);

    __half *p_uw, *p_dw;
    cudaGetSymbolAddress((void**)&p_uw, g_uw);
    cudaGetSymbolAddress((void**)&p_dw, g_dw);

    // Side stream for weight conversion, fork-joined via events (capture-safe).
    // kernel_launch runs only twice (correctness + capture); tiny host objects leak harmlessly.
    cudaStream_t s2;
    cudaEvent_t ev_fork, ev_uw, ev_dw;
    cudaStreamCreateWithFlags(&s2, cudaStreamNonBlocking);
    cudaEventCreateWithFlags(&ev_fork, cudaEventDisableTiming);
    cudaEventCreateWithFlags(&ev_uw,   cudaEventDisableTiming);
    cudaEventCreateWithFlags(&ev_dw,   cudaEventDisableTiming);

    // fork from main stream head
    cudaEventRecord(ev_fork, 0);
    cudaStreamWaitEvent(s2, ev_fork, 0);

    // s2: convert up weights, then down weights (each 32M floats, one float4/thread)
    conv_w_one<<<32768, 256, 0, s2>>>(upW, p_uw);
    cudaEventRecord(ev_uw, s2);
    conv_w_one<<<32768, 256, 0, s2>>>(dW, p_dw);
    cudaEventRecord(ev_dw, s2);

    // main stream: routing chain (independent of weight conversion)
    init_kernel<<<1, 32>>>();
    gate_kernel<<<N_TOK / 8, 256>>>(x, gW, gb, gate_out);
    scan_kernel<<<1, 1>>>();
    scatter_kernel<<<N_TOK / 256, 256>>>();
    conv_x_kernel<<<N_TOK, 256>>>(x);

    // up GEMM needs converted up weights
    cudaStreamWaitEvent(0, ev_uw, 0);
    gemm_kernel<true><<<dim3(DF / 256, MAX_TILES), 512, SMEM_BYTES>>>(upb, nullptr);

    // down GEMM needs converted down weights (conversion overlapped with up GEMM)
    cudaStreamWaitEvent(0, ev_dw, 0);
    gemm_kernel<false><<<dim3(DM / 256, MAX_TILES), 512, SMEM_BYTES>>>(db, out);
}